// round 16
// baseline (speedup 1.0000x reference)
#include <cuda_runtime.h>
#include <cuda_fp16.h>

// DistMult edge scoring: out[e] = sum_d X[src[e],d] * R[rel[e],d] * X[dst[e],d]
//
// Round 15 resubmit (infra failure, kernel unchanged): the kernel is
// ISSUE-bound (R14: issue 76%, alu 49%), so cut instructions/edge. Full-warp
// edges: 32 lanes x 1 uint (2 fp16 dims) = the whole 128B row in ONE
// perfectly-coalesced LDG.32 (still 3 lines/edge). Triple product in half2
// (2 HMUL2) + fp32 pair-accumulate (2 CVT + FADD): 5 math instr/edge vs ~12.
// 9-SHFL folded reduction per 4 edges (R11-verified mapping), contiguous
// 4-lane store. 32-reg tier.
// Error: 5 rounding sources (3 storage + 2 hmul) ~ 4.6e-4 < 1e-3.

constexpr int XDIM      = 64;
constexpr int NUM_NODES = 100000;
constexpr int REL_CAP   = 256;          // >= 237
constexpr int BLOCK     = 256;

// fp16 scratch (static __device__ arrays are the sanctioned scratch path).
__device__ __half2 d_Xh[NUM_NODES * XDIM / 2];   // 12.8 MB
__device__ __half2 d_Rh[REL_CAP   * XDIM / 2];   // 32 KB

// ── Prologue: fp32 -> fp16 conversion (streamed, ~38MB).
__global__ void convert_kernel(const float4* __restrict__ X, int n4x,
                               const float4* __restrict__ Rf, int n4r)
{
    int i = blockIdx.x * blockDim.x + threadIdx.x;
    if (i < n4x) {
        float4 v = __ldcs(X + i);
        __half2 h0 = __floats2half2_rn(v.x, v.y);
        __half2 h1 = __floats2half2_rn(v.z, v.w);
        uint2 p;
        p.x = *reinterpret_cast<unsigned*>(&h0);
        p.y = *reinterpret_cast<unsigned*>(&h1);
        reinterpret_cast<uint2*>(d_Xh)[i] = p;
    }
    if (i < n4r) {
        float4 v = __ldg(Rf + i);
        __half2 h0 = __floats2half2_rn(v.x, v.y);
        __half2 h1 = __floats2half2_rn(v.z, v.w);
        uint2 p;
        p.x = *reinterpret_cast<unsigned*>(&h0);
        p.y = *reinterpret_cast<unsigned*>(&h1);
        reinterpret_cast<uint2*>(d_Rh)[i] = p;
    }
}

__device__ __forceinline__ __half2 u2h(unsigned u) {
    return *reinterpret_cast<__half2*>(&u);
}

// Triple product of one lane's 2 dims in half2, pair-accumulated in fp32.
__device__ __forceinline__ float tprod(unsigned A, unsigned Rr, unsigned B) {
    __half2 p = __hmul2(__hmul2(u2h(A), u2h(Rr)), u2h(B));
    return __low2float(p) + __high2float(p);
}

__global__ __launch_bounds__(BLOCK, 8)
void distmult_kernel(const int* __restrict__ edge_list,  // [2, E]
                     const int* __restrict__ edge_type,  // [1, E]
                     float*     __restrict__ out,        // [E]
                     int num_edges)
{
    int gid    = blockIdx.x * BLOCK + threadIdx.x;
    int wl     = gid & 31;
    int warp   = gid >> 5;
    int e_base = warp * 4;          // 4 edges per warp

    int4 src, dst, rel;
    if (e_base + 3 < num_edges) {
        // Fast path (always taken when E % 4 == 0); broadcast int4 loads.
        src = __ldg(reinterpret_cast<const int4*>(edge_list + e_base));
        dst = __ldg(reinterpret_cast<const int4*>(edge_list + num_edges + e_base));
        rel = __ldg(reinterpret_cast<const int4*>(edge_type + e_base));
    } else {
        int c0 = min(e_base + 0, num_edges - 1);
        int c1 = min(e_base + 1, num_edges - 1);
        int c2 = min(e_base + 2, num_edges - 1);
        int c3 = min(e_base + 3, num_edges - 1);
        src = make_int4(__ldg(&edge_list[c0]), __ldg(&edge_list[c1]),
                        __ldg(&edge_list[c2]), __ldg(&edge_list[c3]));
        dst = make_int4(__ldg(&edge_list[num_edges + c0]), __ldg(&edge_list[num_edges + c1]),
                        __ldg(&edge_list[num_edges + c2]), __ldg(&edge_list[num_edges + c3]));
        rel = make_int4(__ldg(&edge_type[c0]), __ldg(&edge_type[c1]),
                        __ldg(&edge_type[c2]), __ldg(&edge_type[c3]));
    }

    const unsigned* Xu = reinterpret_cast<const unsigned*>(d_Xh);
    const unsigned* Ru = reinterpret_cast<const unsigned*>(d_Rh);
    const int V = XDIM / 2;   // 32 uints per row; lane l -> dims 2l, 2l+1

    // ── All 12 gathers batched (12 scalar regs live, MLP=12). Each warp
    //    instruction: 32 lanes x 4B = one full row = ONE 128B line.
    unsigned A0 = __ldg(Xu + src.x * V + wl);
    unsigned B0 = __ldg(Xu + dst.x * V + wl);
    unsigned R0 = __ldg(Ru + rel.x * V + wl);
    unsigned A1 = __ldg(Xu + src.y * V + wl);
    unsigned B1 = __ldg(Xu + dst.y * V + wl);
    unsigned R1 = __ldg(Ru + rel.y * V + wl);
    unsigned A2 = __ldg(Xu + src.z * V + wl);
    unsigned B2 = __ldg(Xu + dst.z * V + wl);
    unsigned R2 = __ldg(Ru + rel.z * V + wl);
    unsigned A3 = __ldg(Xu + src.w * V + wl);
    unsigned B3 = __ldg(Xu + dst.w * V + wl);
    unsigned R3 = __ldg(Ru + rel.w * V + wl);

    float s0 = tprod(A0, R0, B0);
    float s1 = tprod(A1, R1, B1);
    float s2 = tprod(A2, R2, B2);
    float s3 = tprod(A3, R3, B3);

    // ── Folded warp reduction: 9 SHFLs for 4 edges (R11-verified mapping).
    s0 += __shfl_xor_sync(0xFFFFFFFFu, s0, 16);
    s1 += __shfl_xor_sync(0xFFFFFFFFu, s1, 16);
    s2 += __shfl_xor_sync(0xFFFFFFFFu, s2, 16);
    s3 += __shfl_xor_sync(0xFFFFFFFFu, s3, 16);
    float a = (wl & 16) ? s1 : s0;   // halves: edge0 (lanes 0-15), edge1 (16-31)
    float b = (wl & 16) ? s3 : s2;   // halves: edge2, edge3
    a += __shfl_xor_sync(0xFFFFFFFFu, a, 8);
    b += __shfl_xor_sync(0xFFFFFFFFu, b, 8);
    float c = (wl & 8) ? b : a;
    // octets: lanes0-7 e0, 8-15 e2, 16-23 e1, 24-31 e3
    c += __shfl_xor_sync(0xFFFFFFFFu, c, 4);
    c += __shfl_xor_sync(0xFFFFFFFFu, c, 2);
    c += __shfl_xor_sync(0xFFFFFFFFu, c, 1);

    // lane0 -> e_base, lane8 -> e_base+2, lane16 -> e_base+1, lane24 -> e_base+3
    if ((wl & 7) == 0) {
        int off = ((wl >> 4) & 1) | (((wl >> 3) & 1) << 1);
        int e = e_base + off;
        if (e < num_edges)
            out[e] = c;
    }
}

extern "C" void kernel_launch(void* const* d_in, const int* in_sizes, int n_in,
                              void* d_out, int out_size)
{
    const float* X  = (const float*)d_in[0];   // [100000, 64]
    const float* R  = (const float*)d_in[1];   // [237, 64]
    const int* edge_list = (const int*)d_in[2];
    const int* edge_type = (const int*)d_in[3];
    float* out = (float*)d_out;

    int num_edges = in_sizes[3];
    int n4x = in_sizes[0] / 4;                 // 1,600,000
    int n4r = in_sizes[1] / 4;                 // 3,792

    int n4max = n4x > n4r ? n4x : n4r;
    int cgrid = (n4max + 255) / 256;
    convert_kernel<<<cgrid, 256>>>((const float4*)X, n4x,
                                   (const float4*)R, n4r);

    int warps = (num_edges + 3) / 4;           // 4 edges per warp
    long long total_threads = (long long)warps * 32;
    int grid = (int)((total_threads + BLOCK - 1) / BLOCK);
    distmult_kernel<<<grid, BLOCK>>>(edge_list, edge_type, out, num_edges);
}

// round 17
// speedup vs baseline: 1.5787x; 1.5787x over previous
#include <cuda_runtime.h>
#include <cuda_fp16.h>

// DistMult edge scoring: out[e] = sum_d X[src[e],d] * R[rel[e],d] * X[dst[e],d]
//
// Round 17: R14 champion structure (16-lane groups x 2 per warp-instruction,
// uint2 half4 row-halves, 12 batched gathers, folded 8-SHFL reduction,
// 32-reg tier) with ONE change: the dot-product math is half2
// (4 HMUL2 + 1 HADD2 + 2 CVT + 1 FADD per edge-slice) instead of
// 12 converts + ~16 fp32 ops. R16 lesson: count WARP-instructions/edge —
// R14's two-groups-per-instruction amortization is load-bearing; R15's
// full-warp edges doubled per-edge cost. This applies R15's math savings
// inside R14's memory shape.
// Error: 6 rounding sources (3 storage + 2 hmul + 1 hadd) ~ 5.1e-4 < 1e-3.

constexpr int XDIM      = 64;
constexpr int NUM_NODES = 100000;
constexpr int REL_CAP   = 256;          // >= 237
constexpr int LANES     = 16;
constexpr int EPG       = 4;            // edges per 16-lane group
constexpr int BLOCK     = 256;

// fp16 scratch (static __device__ arrays are the sanctioned scratch path).
__device__ __half2 d_Xh[NUM_NODES * XDIM / 2];   // 12.8 MB
__device__ __half2 d_Rh[REL_CAP   * XDIM / 2];   // 32 KB

// ── Prologue: fp32 -> fp16 conversion (streamed, ~38MB).
__global__ void convert_kernel(const float4* __restrict__ X, int n4x,
                               const float4* __restrict__ Rf, int n4r)
{
    int i = blockIdx.x * blockDim.x + threadIdx.x;
    if (i < n4x) {
        float4 v = __ldcs(X + i);
        __half2 h0 = __floats2half2_rn(v.x, v.y);
        __half2 h1 = __floats2half2_rn(v.z, v.w);
        uint2 p;
        p.x = *reinterpret_cast<unsigned*>(&h0);
        p.y = *reinterpret_cast<unsigned*>(&h1);
        reinterpret_cast<uint2*>(d_Xh)[i] = p;
    }
    if (i < n4r) {
        float4 v = __ldg(Rf + i);
        __half2 h0 = __floats2half2_rn(v.x, v.y);
        __half2 h1 = __floats2half2_rn(v.z, v.w);
        uint2 p;
        p.x = *reinterpret_cast<unsigned*>(&h0);
        p.y = *reinterpret_cast<unsigned*>(&h1);
        reinterpret_cast<uint2*>(d_Rh)[i] = p;
    }
}

__device__ __forceinline__ __half2 u2h(unsigned u) {
    return *reinterpret_cast<__half2*>(&u);
}

// Triple product over one lane's 4 dims, half2 math, fp32 final pair-add.
__device__ __forceinline__ float tprod(uint2 A, uint2 Rr, uint2 B) {
    __half2 p0 = __hmul2(__hmul2(u2h(A.x), u2h(Rr.x)), u2h(B.x));
    __half2 p1 = __hmul2(__hmul2(u2h(A.y), u2h(Rr.y)), u2h(B.y));
    __half2 q  = __hadd2(p0, p1);
    return __low2float(q) + __high2float(q);
}

__global__ __launch_bounds__(BLOCK, 8)
void distmult_kernel(const int* __restrict__ edge_list,  // [2, E]
                     const int* __restrict__ edge_type,  // [1, E]
                     float*     __restrict__ out,        // [E]
                     int num_edges)
{
    int gid   = blockIdx.x * BLOCK + threadIdx.x;
    int group = gid >> 4;
    int lane  = gid & (LANES - 1);

    int e0 = group * EPG;

    int4 src, dst, rel;
    if (e0 + 3 < num_edges) {
        src = __ldg(reinterpret_cast<const int4*>(edge_list + e0));
        dst = __ldg(reinterpret_cast<const int4*>(edge_list + num_edges + e0));
        rel = __ldg(reinterpret_cast<const int4*>(edge_type + e0));
    } else {
        int c0 = min(e0 + 0, num_edges - 1);
        int c1 = min(e0 + 1, num_edges - 1);
        int c2 = min(e0 + 2, num_edges - 1);
        int c3 = min(e0 + 3, num_edges - 1);
        src = make_int4(__ldg(&edge_list[c0]), __ldg(&edge_list[c1]),
                        __ldg(&edge_list[c2]), __ldg(&edge_list[c3]));
        dst = make_int4(__ldg(&edge_list[num_edges + c0]), __ldg(&edge_list[num_edges + c1]),
                        __ldg(&edge_list[num_edges + c2]), __ldg(&edge_list[num_edges + c3]));
        rel = make_int4(__ldg(&edge_type[c0]), __ldg(&edge_type[c1]),
                        __ldg(&edge_type[c2]), __ldg(&edge_type[c3]));
    }

    const uint2* Xh = reinterpret_cast<const uint2*>(d_Xh);
    const uint2* Rh = reinterpret_cast<const uint2*>(d_Rh);
    const int V = XDIM / 4;   // 16 uint2 (half4) per row

    // ── All 12 gathers batched (24 regs live, MLP=12). Each warp
    //    instruction: 2 groups x 1 line = 2 lines; 3 lines/edge total.
    uint2 A0 = __ldg(Xh + src.x * V + lane);
    uint2 B0 = __ldg(Xh + dst.x * V + lane);
    uint2 R0 = __ldg(Rh + rel.x * V + lane);
    uint2 A1 = __ldg(Xh + src.y * V + lane);
    uint2 B1 = __ldg(Xh + dst.y * V + lane);
    uint2 R1 = __ldg(Rh + rel.y * V + lane);
    uint2 A2 = __ldg(Xh + src.z * V + lane);
    uint2 B2 = __ldg(Xh + dst.z * V + lane);
    uint2 R2 = __ldg(Rh + rel.z * V + lane);
    uint2 A3 = __ldg(Xh + src.w * V + lane);
    uint2 B3 = __ldg(Xh + dst.w * V + lane);
    uint2 R3 = __ldg(Rh + rel.w * V + lane);

    float s0 = tprod(A0, R0, B0);
    float s1 = tprod(A1, R1, B1);
    float s2 = tprod(A2, R2, B2);
    float s3 = tprod(A3, R3, B3);

    // ── Folded reduction, strictly after all loads: 8 SHFLs for 4 edges.
    s0 += __shfl_xor_sync(0xFFFFFFFFu, s0, 8);
    s1 += __shfl_xor_sync(0xFFFFFFFFu, s1, 8);
    s2 += __shfl_xor_sync(0xFFFFFFFFu, s2, 8);
    s3 += __shfl_xor_sync(0xFFFFFFFFu, s3, 8);
    float a = (lane & 8) ? s1 : s0;   // edge0 lanes 0-7, edge1 lanes 8-15
    float b = (lane & 8) ? s3 : s2;   // edge2 lanes 0-7, edge3 lanes 8-15
    a += __shfl_xor_sync(0xFFFFFFFFu, a, 4);
    b += __shfl_xor_sync(0xFFFFFFFFu, b, 4);
    float c = (lane & 4) ? b : a;
    // quads: lanes0-3 e0, 4-7 e2, 8-11 e1, 12-15 e3
    c += __shfl_xor_sync(0xFFFFFFFFu, c, 2);
    c += __shfl_xor_sync(0xFFFFFFFFu, c, 1);

    if ((lane & 3) == 0) {
        int off = ((lane >> 3) & 1) | (((lane >> 2) & 1) << 1);
        int e = e0 + off;
        if (e < num_edges)
            out[e] = c;
    }
}

extern "C" void kernel_launch(void* const* d_in, const int* in_sizes, int n_in,
                              void* d_out, int out_size)
{
    const float* X  = (const float*)d_in[0];   // [100000, 64]
    const float* R  = (const float*)d_in[1];   // [237, 64]
    const int* edge_list = (const int*)d_in[2];
    const int* edge_type = (const int*)d_in[3];
    float* out = (float*)d_out;

    int num_edges = in_sizes[3];
    int n4x = in_sizes[0] / 4;                 // 1,600,000
    int n4r = in_sizes[1] / 4;                 // 3,792

    int n4max = n4x > n4r ? n4x : n4r;
    int cgrid = (n4max + 255) / 256;
    convert_kernel<<<cgrid, 256>>>((const float4*)X, n4x,
                                   (const float4*)R, n4r);

    int groups = (num_edges + EPG - 1) / EPG;
    long long total_threads = (long long)groups * LANES;
    int grid = (int)((total_threads + BLOCK - 1) / BLOCK);
    distmult_kernel<<<grid, BLOCK>>>(edge_list, edge_type, out, num_edges);
}